// round 15
// baseline (speedup 1.0000x reference)
#include <cuda_runtime.h>

// ---------------- problem constants (fixed shapes) ----------------
constexpr int   NN   = 100000;   // nodes
constexpr int   NE   = 1600000;  // edges
constexpr int   FIN  = 128;
constexpr int   HID  = 64;
constexpr int   TOUT = 10;
constexpr int   NB   = (NN + 255) / 256;   // 391 node blocks
constexpr int   NG   = NN / 4;             // 25000 row groups of 4
constexpr int   NSM  = 148;                // sm_100a SM count
#define ALPHA 0.1f

// ---------------- f32x2 packed math helpers ----------------
__device__ __forceinline__ unsigned long long pack2(float x, float y) {
    unsigned long long r;
    asm("mov.b64 %0, {%1, %2};" : "=l"(r) : "f"(x), "f"(y));
    return r;
}
__device__ __forceinline__ void ffma2(unsigned long long& d,
                                      unsigned long long a, unsigned long long b) {
    asm("fma.rn.f32x2 %0, %1, %2, %0;" : "+l"(d) : "l"(a), "l"(b));
}

// ---------------- device scratch (no allocations allowed) ----------------
__device__ int   g_is64;           // 1 if edge_index buffer is int64
__device__ int2  g_edge[NE];       // (row, col) as int32
__device__ float g_w[NE];          // decay
__device__ float g_deg[NN];        // out-degree (decay-weighted)
__device__ float g_dinv2[NN];      // deg2 accumulator, then dinv2
__device__ int   g_cnt[NN];        // in-degree counts (by col)
__device__ int   g_bsum[NB];       // scan: per-block sums
__device__ int   g_ptr[NN + 1];    // CSR row pointers (by col)
__device__ int   g_pos[NN];        // fill cursors
__device__ int2  g_csre[NE];       // CSR edge records {src, raw-ew bits}
__device__ float g_HA[NN * HID];   // H0, later overwritten by H1b
__device__ float g_AG[NN * HID];   // aggregation output (written once/node)

// ---------------- kernels ----------------

__global__ void k_detect_zero(const int* __restrict__ ei32) {
    int i = blockIdx.x * blockDim.x + threadIdx.x;
    if (i == 0) {
        int odd_or = 0;
        #pragma unroll
        for (int k = 1; k < 64; k += 2) odd_or |= ei32[k];
        g_is64 = (odd_or == 0) ? 1 : 0;
    }
    if (i < NN) { g_deg[i] = 0.f; g_dinv2[i] = 0.f; g_cnt[i] = 0; }
}

// decay = exp(alpha*t)  [exp(-alpha*tmax) cancels in the symmetric norm];
// deg[row] += decay; cnt[col]++
__global__ void k_decay_deg(const int* __restrict__ ei, const float* __restrict__ t) {
    int e = blockIdx.x * blockDim.x + threadIdx.x;
    if (e >= NE) return;
    int r, c;
    if (g_is64) {
        const long long* e64 = (const long long*)ei;
        r = (int)e64[e];
        c = (int)e64[NE + e];
    } else {
        r = ei[e];
        c = ei[NE + e];
    }
    g_edge[e] = make_int2(r, c);
    float d = expf(ALPHA * t[e]);
    g_w[e] = d;
    atomicAdd(&g_deg[r], d);
    atomicAdd(&g_cnt[c], 1);
}

// ---- scan phase A: per-block sums of g_cnt ----
__global__ void k_scanA() {
    __shared__ int sm[8];
    int i = blockIdx.x * blockDim.x + threadIdx.x;
    int v = (i < NN) ? g_cnt[i] : 0;
    #pragma unroll
    for (int o = 16; o; o >>= 1) v += __shfl_xor_sync(0xffffffffu, v, o);
    if ((threadIdx.x & 31) == 0) sm[threadIdx.x >> 5] = v;
    __syncthreads();
    if (threadIdx.x < 8) {
        v = sm[threadIdx.x];
        #pragma unroll
        for (int o = 4; o; o >>= 1) v += __shfl_xor_sync(0xffu, v, o);
        if (threadIdx.x == 0) g_bsum[blockIdx.x] = v;
    }
}

// ---- scan phase C (fused B): block reduces its bsum prefix, scans its 256
// counts -> ptr/pos ----
__global__ void k_scanC() {
    __shared__ int ws[8];
    __shared__ int sbase;
    int t = threadIdx.x, lane = t & 31, wid = t >> 5;
    int bid = blockIdx.x;

    int off = 0;
    for (int j = t; j < bid; j += 256) off += g_bsum[j];
    #pragma unroll
    for (int o = 16; o; o >>= 1) off += __shfl_xor_sync(0xffffffffu, off, o);
    if (lane == 0) ws[wid] = off;
    __syncthreads();
    if (t == 0) {
        int b = 0;
        #pragma unroll
        for (int j = 0; j < 8; j++) b += ws[j];
        sbase = b;
    }
    __syncthreads();
    int base = sbase;
    __syncthreads();   // ws reused below

    int i = bid * 256 + t;
    int c = (i < NN) ? g_cnt[i] : 0;
    int inc = c;
    #pragma unroll
    for (int o = 1; o < 32; o <<= 1) {
        int u = __shfl_up_sync(0xffffffffu, inc, o);
        if (lane >= o) inc += u;
    }
    if (lane == 31) ws[wid] = inc;
    __syncthreads();
    if (wid == 0 && lane < 8) {
        int w = ws[lane];
        #pragma unroll
        for (int o = 1; o < 8; o <<= 1) {
            int u = __shfl_up_sync(0xffu, w, o);
            if (lane >= o) w += u;
        }
        ws[lane] = w;
    }
    __syncthreads();
    int ex = inc - c + (wid ? ws[wid - 1] : 0) + base;
    if (i < NN) { g_ptr[i] = ex; g_pos[i] = ex; }
    if (i == NN - 1) g_ptr[NN] = ex + c;
}

// fused ew + CSR fill: ew = dinv[row]*decay*dinv[col]; deg2[col] += ew;
// csre[pos[col]++] = {row, raw ew}. The dinv2 factors are applied in spmm.
__global__ void k_ew_fill() {
    int e = blockIdx.x * blockDim.x + threadIdx.x;
    if (e >= NE) return;
    int2 rc = g_edge[e];
    float dr = g_deg[rc.x];
    float dc = g_deg[rc.y];
    float ir = (dr > 0.f) ? rsqrtf(dr) : 0.f;
    float ic = (dc > 0.f) ? rsqrtf(dc) : 0.f;
    float ew = ir * g_w[e] * ic;
    atomicAdd(&g_dinv2[rc.y], ew);          // deg2 accumulation
    int p = atomicAdd(&g_pos[rc.y], 1);
    g_csre[p] = make_int2(rc.x, __float_as_int(ew));
}

// finalize dinv2 = rsqrt(deg2 + 1)
__global__ void k_fin() {
    int i = blockIdx.x * blockDim.x + threadIdx.x;
    if (i >= NN) return;
    g_dinv2[i] = rsqrtf(g_dinv2[i] + 1.0f);
}

// HA = x @ W1: persistent grid-stride; thread computes 4 rows x 16 cols
__global__ void __launch_bounds__(256, 2)
k_gemm1(const float* __restrict__ x, const float* __restrict__ W1) {
    __shared__ float Ws[FIN * HID]; // 32 KB
    {
        const float4* w4 = (const float4*)W1;
        float4* s4 = (float4*)Ws;
        for (int i = threadIdx.x; i < FIN * HID / 4; i += blockDim.x) s4[i] = w4[i];
    }
    __syncthreads();
    for (int gt = blockIdx.x * blockDim.x + threadIdx.x; gt < NG * 4;
         gt += gridDim.x * blockDim.x) {
        int grp   = gt >> 2;
        int slice = gt & 3;
        int r0 = grp * 4;
        const float4* xr0 = (const float4*)(x + (long)(r0 + 0) * FIN);
        const float4* xr1 = (const float4*)(x + (long)(r0 + 1) * FIN);
        const float4* xr2 = (const float4*)(x + (long)(r0 + 2) * FIN);
        const float4* xr3 = (const float4*)(x + (long)(r0 + 3) * FIN);
        unsigned long long acc[4][8];
        #pragma unroll
        for (int i = 0; i < 4; i++)
            #pragma unroll
            for (int j = 0; j < 8; j++) acc[i][j] = 0ull;
        const int cb = slice * 16;
        #pragma unroll 2
        for (int k4 = 0; k4 < FIN / 4; k4++) {
            float4 xv[4] = { xr0[k4], xr1[k4], xr2[k4], xr3[k4] };
            #pragma unroll
            for (int kk = 0; kk < 4; kk++) {
                const ulonglong2* wr = (const ulonglong2*)&Ws[(k4 * 4 + kk) * HID + cb];
                ulonglong2 p0 = wr[0], p1 = wr[1], p2 = wr[2], p3 = wr[3];
                unsigned long long w[8] = { p0.x, p0.y, p1.x, p1.y, p2.x, p2.y, p3.x, p3.y };
                #pragma unroll
                for (int i = 0; i < 4; i++) {
                    float xs = (kk == 0) ? xv[i].x : (kk == 1) ? xv[i].y
                             : (kk == 2) ? xv[i].z : xv[i].w;
                    unsigned long long xs2 = pack2(xs, xs);
                    #pragma unroll
                    for (int j = 0; j < 8; j++) ffma2(acc[i][j], xs2, w[j]);
                }
            }
        }
        #pragma unroll
        for (int i = 0; i < 4; i++) {
            ulonglong2* dst = (ulonglong2*)(g_HA + (long)(r0 + i) * HID + cb);
            #pragma unroll
            for (int j = 0; j < 4; j++)
                dst[j] = make_ulonglong2(acc[i][2 * j], acc[i][2 * j + 1]);
        }
    }
}

// gather-SpMM with on-the-fly normalization:
// AG[i] = dinv2[i] * ( sum_e ew_e * dinv2[src_e] * H[src_e] + dinv2[i]*H[i] )
__global__ void k_spmm_csr() {
    int i = (blockIdx.x * blockDim.x + threadIdx.x) >> 5;
    if (i >= NN) return;
    int lane = threadIdx.x & 31;
    int beg = g_ptr[i], end = g_ptr[i + 1];
    float  di = g_dinv2[i];
    float2 h  = ((const float2*)(g_HA + (long)i * HID))[lane];
    float a0 = di * h.x, a1 = di * h.y;       // self term (inside parens)
    int e = beg;
    for (; e + 4 <= end; e += 4) {
        int2 r0 = g_csre[e + 0];
        int2 r1 = g_csre[e + 1];
        int2 r2 = g_csre[e + 2];
        int2 r3 = g_csre[e + 3];
        float s0 = g_dinv2[r0.x], s1 = g_dinv2[r1.x];
        float s2 = g_dinv2[r2.x], s3 = g_dinv2[r3.x];
        float2 v0 = ((const float2*)(g_HA + (long)r0.x * HID))[lane];
        float2 v1 = ((const float2*)(g_HA + (long)r1.x * HID))[lane];
        float2 v2 = ((const float2*)(g_HA + (long)r2.x * HID))[lane];
        float2 v3 = ((const float2*)(g_HA + (long)r3.x * HID))[lane];
        float n0 = __int_as_float(r0.y) * s0;
        float n1 = __int_as_float(r1.y) * s1;
        float n2 = __int_as_float(r2.y) * s2;
        float n3 = __int_as_float(r3.y) * s3;
        a0 += n0 * v0.x; a1 += n0 * v0.y;
        a0 += n1 * v1.x; a1 += n1 * v1.y;
        a0 += n2 * v2.x; a1 += n2 * v2.y;
        a0 += n3 * v3.x; a1 += n3 * v3.y;
    }
    for (; e < end; e++) {
        int2  rec = g_csre[e];
        float nm  = __int_as_float(rec.y) * g_dinv2[rec.x];
        float2 v  = ((const float2*)(g_HA + (long)rec.x * HID))[lane];
        a0 += nm * v.x;
        a1 += nm * v.y;
    }
    ((float2*)(g_AG + (long)i * HID))[lane] = make_float2(di * a0, di * a1);
}

// h1 = relu(AG + b1); HA <- h1 @ W2 : persistent grid-stride, 4x16 tile
__global__ void __launch_bounds__(256, 2)
k_layer1(const float* __restrict__ b1, const float* __restrict__ W2) {
    __shared__ float Ws[HID * HID]; // 16 KB
    __shared__ float bs[HID];
    {
        const float4* w4 = (const float4*)W2;
        float4* s4 = (float4*)Ws;
        for (int i = threadIdx.x; i < HID * HID / 4; i += blockDim.x) s4[i] = w4[i];
        if (threadIdx.x < HID) bs[threadIdx.x] = b1[threadIdx.x];
    }
    __syncthreads();
    for (int gt = blockIdx.x * blockDim.x + threadIdx.x; gt < NG * 4;
         gt += gridDim.x * blockDim.x) {
        int grp   = gt >> 2;
        int slice = gt & 3;
        int r0 = grp * 4;
        const float4* a0p = (const float4*)(g_AG + (long)(r0 + 0) * HID);
        const float4* a1p = (const float4*)(g_AG + (long)(r0 + 1) * HID);
        const float4* a2p = (const float4*)(g_AG + (long)(r0 + 2) * HID);
        const float4* a3p = (const float4*)(g_AG + (long)(r0 + 3) * HID);
        const float4* b4  = (const float4*)bs;
        unsigned long long acc[4][8];
        #pragma unroll
        for (int i = 0; i < 4; i++)
            #pragma unroll
            for (int j = 0; j < 8; j++) acc[i][j] = 0ull;
        const int cb = slice * 16;
        #pragma unroll 2
        for (int k4 = 0; k4 < HID / 4; k4++) {
            float4 bv = b4[k4];
            float4 av[4] = { a0p[k4], a1p[k4], a2p[k4], a3p[k4] };
            float hs[4][4];
            #pragma unroll
            for (int i = 0; i < 4; i++) {
                hs[i][0] = fmaxf(av[i].x + bv.x, 0.f);
                hs[i][1] = fmaxf(av[i].y + bv.y, 0.f);
                hs[i][2] = fmaxf(av[i].z + bv.z, 0.f);
                hs[i][3] = fmaxf(av[i].w + bv.w, 0.f);
            }
            #pragma unroll
            for (int kk = 0; kk < 4; kk++) {
                const ulonglong2* wr = (const ulonglong2*)&Ws[(k4 * 4 + kk) * HID + cb];
                ulonglong2 p0 = wr[0], p1 = wr[1], p2 = wr[2], p3 = wr[3];
                unsigned long long w[8] = { p0.x, p0.y, p1.x, p1.y, p2.x, p2.y, p3.x, p3.y };
                #pragma unroll
                for (int i = 0; i < 4; i++) {
                    unsigned long long xs2 = pack2(hs[i][kk], hs[i][kk]);
                    #pragma unroll
                    for (int j = 0; j < 8; j++) ffma2(acc[i][j], xs2, w[j]);
                }
            }
        }
        #pragma unroll
        for (int i = 0; i < 4; i++) {
            ulonglong2* dst = (ulonglong2*)(g_HA + (long)(r0 + i) * HID + cb);
            #pragma unroll
            for (int j = 0; j < 4; j++)
                dst[j] = make_ulonglong2(acc[i][2 * j], acc[i][2 * j + 1]);
        }
    }
}

// h2 = relu(AG + b2); out = h2 @ Wout + bout : thread per row
__global__ void k_out(const float* __restrict__ b2, const float* __restrict__ Wout,
                      const float* __restrict__ bout, float* __restrict__ out) {
    __shared__ float Ws[HID * TOUT];
    __shared__ float bs[HID];
    __shared__ float bo[TOUT];
    for (int i = threadIdx.x; i < HID * TOUT; i += blockDim.x) Ws[i] = Wout[i];
    if (threadIdx.x < HID)  bs[threadIdx.x] = b2[threadIdx.x];
    if (threadIdx.x < TOUT) bo[threadIdx.x] = bout[threadIdx.x];
    __syncthreads();
    int row = blockIdx.x * blockDim.x + threadIdx.x;
    if (row >= NN) return;
    const float4* ar = (const float4*)(g_AG + (long)row * HID);
    const float4* b4 = (const float4*)bs;
    float acc[TOUT];
    #pragma unroll
    for (int j = 0; j < TOUT; j++) acc[j] = bo[j];
    #pragma unroll 2
    for (int k4 = 0; k4 < HID / 4; k4++) {
        float4 av = ar[k4];
        float4 bv = b4[k4];
        float hs[4] = { fmaxf(av.x + bv.x, 0.f), fmaxf(av.y + bv.y, 0.f),
                        fmaxf(av.z + bv.z, 0.f), fmaxf(av.w + bv.w, 0.f) };
        #pragma unroll
        for (int kk = 0; kk < 4; kk++) {
            float xs = hs[kk];
            const float* wr = &Ws[(k4 * 4 + kk) * TOUT];
            #pragma unroll
            for (int j = 0; j < TOUT; j++) acc[j] += xs * wr[j];
        }
    }
    float* o = out + (long)row * TOUT;
    #pragma unroll
    for (int j = 0; j < TOUT; j++) o[j] = acc[j];
}

// ---------------- launch ----------------
extern "C" void kernel_launch(void* const* d_in, const int* in_sizes, int n_in,
                              void* d_out, int out_size) {
    const float* x    = (const float*)d_in[0];
    const int*   ei   = (const int*)d_in[1];
    const float* et   = (const float*)d_in[2];
    const float* W1   = (const float*)d_in[3];
    const float* b1   = (const float*)d_in[4];
    const float* W2   = (const float*)d_in[5];
    const float* b2   = (const float*)d_in[6];
    const float* Wout = (const float*)d_in[7];
    const float* bout = (const float*)d_in[8];
    float*       out  = (float*)d_out;

    const int TB = 256;
    const int GEMMB = 2 * NSM;          // one full resident wave

    cudaStream_t s2;
    cudaEvent_t  eFork, eJoin;
    cudaStreamCreateWithFlags(&s2, cudaStreamNonBlocking);
    cudaEventCreateWithFlags(&eFork, cudaEventDisableTiming);
    cudaEventCreateWithFlags(&eJoin, cudaEventDisableTiming);

    // fork: gemm1 runs concurrently with the edge-preprocessing chain
    cudaEventRecord(eFork, 0);
    cudaStreamWaitEvent(s2, eFork, 0);
    k_gemm1<<<GEMMB, TB, 0, s2>>>(x, W1);
    cudaEventRecord(eJoin, s2);

    // main stream: edge preprocessing -> CSR (fill fused into ew pass)
    k_detect_zero<<<NB, TB>>>(ei);
    k_decay_deg<<<(NE + TB - 1) / TB, TB>>>(ei, et);
    k_scanA<<<NB, TB>>>();
    k_scanC<<<NB, TB>>>();
    k_ew_fill<<<(NE + TB - 1) / TB, TB>>>();
    k_fin<<<NB, TB>>>();

    // join: spmm needs both HA (gemm1) and CSR (ew_fill) + dinv2 (fin)
    cudaStreamWaitEvent(0, eJoin, 0);

    k_spmm_csr<<<(NN * 32 + TB - 1) / TB, TB>>>();
    k_layer1<<<GEMMB, TB>>>(b1, W2);
    k_spmm_csr<<<(NN * 32 + TB - 1) / TB, TB>>>();
    k_out<<<NB, TB>>>(b2, Wout, bout, out);
}

// round 16
// speedup vs baseline: 1.0034x; 1.0034x over previous
#include <cuda_runtime.h>

// ---------------- problem constants (fixed shapes) ----------------
constexpr int   NN   = 100000;   // nodes
constexpr int   NE   = 1600000;  // edges
constexpr int   FIN  = 128;
constexpr int   HID  = 64;
constexpr int   TOUT = 10;
constexpr int   NB   = (NN + 255) / 256;   // 391 node blocks
constexpr int   NG   = NN / 4;             // 25000 row groups of 4
constexpr int   NSM  = 148;                // sm_100a SM count
#define ALPHA 0.1f

// ---------------- f32x2 packed math helpers ----------------
__device__ __forceinline__ unsigned long long pack2(float x, float y) {
    unsigned long long r;
    asm("mov.b64 %0, {%1, %2};" : "=l"(r) : "f"(x), "f"(y));
    return r;
}
__device__ __forceinline__ void ffma2(unsigned long long& d,
                                      unsigned long long a, unsigned long long b) {
    asm("fma.rn.f32x2 %0, %1, %2, %0;" : "+l"(d) : "l"(a), "l"(b));
}
__device__ __forceinline__ void unpack2(unsigned long long v, float& lo, float& hi) {
    asm("mov.b64 {%0, %1}, %2;" : "=f"(lo), "=f"(hi) : "l"(v));
}

// ---------------- device scratch (no allocations allowed) ----------------
__device__ int   g_is64;           // 1 if edge_index buffer is int64
__device__ int2  g_edge[NE];       // (row, col) as int32
__device__ float g_w[NE];          // decay -> ew (in place)
__device__ float g_deg[NN];        // out-degree (decay-weighted)
__device__ float g_dinv2[NN];      // deg2 accumulator, then dinv2
__device__ float g_nself[NN];      // self-loop norm = dinv2^2
__device__ int   g_cnt[NN];        // in-degree counts (by col)
__device__ int   g_bsum[NB];       // scan: per-block sums
__device__ int   g_ptr[NN + 1];    // CSR row pointers (by col)
__device__ int   g_pos[NN];        // fill cursors
__device__ int2  g_csre[NE];       // CSR edge records {src, norm bits}
__device__ float g_HA[NN * HID];   // H0, then P = A_hat * H1
__device__ float g_AG[NN * HID];   // H1 = relu(A_hat*H0 + b1)

// ---------------- kernels ----------------

__global__ void k_detect_zero(const int* __restrict__ ei32) {
    int i = blockIdx.x * blockDim.x + threadIdx.x;
    if (i == 0) {
        int odd_or = 0;
        #pragma unroll
        for (int k = 1; k < 64; k += 2) odd_or |= ei32[k];
        g_is64 = (odd_or == 0) ? 1 : 0;
    }
    if (i < NN) { g_deg[i] = 0.f; g_dinv2[i] = 0.f; g_cnt[i] = 0; }
}

// decay = exp(alpha*t) [exp(-alpha*tmax) cancels]; deg[row]+=decay; cnt[col]++
__global__ void k_decay_deg(const int* __restrict__ ei, const float* __restrict__ t) {
    int e = blockIdx.x * blockDim.x + threadIdx.x;
    if (e >= NE) return;
    int r, c;
    if (g_is64) {
        const long long* e64 = (const long long*)ei;
        r = (int)e64[e];
        c = (int)e64[NE + e];
    } else {
        r = ei[e];
        c = ei[NE + e];
    }
    g_edge[e] = make_int2(r, c);
    float d = expf(ALPHA * t[e]);
    g_w[e] = d;
    atomicAdd(&g_deg[r], d);
    atomicAdd(&g_cnt[c], 1);
}

// ew = dinv[row]*decay*dinv[col] (dinv on the fly); deg2[col] += ew
__global__ void k_ew_deg2() {
    int e = blockIdx.x * blockDim.x + threadIdx.x;
    if (e >= NE) return;
    int2 rc = g_edge[e];
    float dr = g_deg[rc.x];
    float dc = g_deg[rc.y];
    float ir = (dr > 0.f) ? rsqrtf(dr) : 0.f;
    float ic = (dc > 0.f) ? rsqrtf(dc) : 0.f;
    float ew = ir * g_w[e] * ic;
    g_w[e] = ew;
    atomicAdd(&g_dinv2[rc.y], ew);
}

// ---- scan phase A: per-block sums of g_cnt ----
__global__ void k_scanA() {
    __shared__ int sm[8];
    int i = blockIdx.x * blockDim.x + threadIdx.x;
    int v = (i < NN) ? g_cnt[i] : 0;
    #pragma unroll
    for (int o = 16; o; o >>= 1) v += __shfl_xor_sync(0xffffffffu, v, o);
    if ((threadIdx.x & 31) == 0) sm[threadIdx.x >> 5] = v;
    __syncthreads();
    if (threadIdx.x < 8) {
        v = sm[threadIdx.x];
        #pragma unroll
        for (int o = 4; o; o >>= 1) v += __shfl_xor_sync(0xffu, v, o);
        if (threadIdx.x == 0) g_bsum[blockIdx.x] = v;
    }
}

// ---- scan phase C (fused B): ptr/pos + dinv2/nself finalize ----
__global__ void k_scanC() {
    __shared__ int ws[8];
    __shared__ int sbase;
    int t = threadIdx.x, lane = t & 31, wid = t >> 5;
    int bid = blockIdx.x;

    int off = 0;
    for (int j = t; j < bid; j += 256) off += g_bsum[j];
    #pragma unroll
    for (int o = 16; o; o >>= 1) off += __shfl_xor_sync(0xffffffffu, off, o);
    if (lane == 0) ws[wid] = off;
    __syncthreads();
    if (t == 0) {
        int b = 0;
        #pragma unroll
        for (int j = 0; j < 8; j++) b += ws[j];
        sbase = b;
    }
    __syncthreads();
    int base = sbase;
    __syncthreads();   // ws reused below

    int i = bid * 256 + t;
    int c = (i < NN) ? g_cnt[i] : 0;
    int inc = c;
    #pragma unroll
    for (int o = 1; o < 32; o <<= 1) {
        int u = __shfl_up_sync(0xffffffffu, inc, o);
        if (lane >= o) inc += u;
    }
    if (lane == 31) ws[wid] = inc;
    __syncthreads();
    if (wid == 0 && lane < 8) {
        int w = ws[lane];
        #pragma unroll
        for (int o = 1; o < 8; o <<= 1) {
            int u = __shfl_up_sync(0xffu, w, o);
            if (lane >= o) w += u;
        }
        ws[lane] = w;
    }
    __syncthreads();
    int ex = inc - c + (wid ? ws[wid - 1] : 0) + base;
    if (i < NN) {
        g_ptr[i] = ex;
        g_pos[i] = ex;
        float d2 = g_dinv2[i] + 1.0f;     // + self loop weight 1
        float di = rsqrtf(d2);
        g_dinv2[i] = di;
        g_nself[i] = di * di;
    }
    if (i == NN - 1) g_ptr[NN] = ex + c;
}

__global__ void k_fill() {
    int e = blockIdx.x * blockDim.x + threadIdx.x;
    if (e >= NE) return;
    int2 rc = g_edge[e];
    float nm = g_dinv2[rc.x] * g_w[e] * g_dinv2[rc.y];
    int p = atomicAdd(&g_pos[rc.y], 1);
    g_csre[p] = make_int2(rc.x, __float_as_int(nm));
}

// HA = x @ W1: persistent grid-stride; thread computes 4 rows x 16 cols
__global__ void __launch_bounds__(256, 2)
k_gemm1(const float* __restrict__ x, const float* __restrict__ W1) {
    __shared__ float Ws[FIN * HID]; // 32 KB
    {
        const float4* w4 = (const float4*)W1;
        float4* s4 = (float4*)Ws;
        for (int i = threadIdx.x; i < FIN * HID / 4; i += blockDim.x) s4[i] = w4[i];
    }
    __syncthreads();
    for (int gt = blockIdx.x * blockDim.x + threadIdx.x; gt < NG * 4;
         gt += gridDim.x * blockDim.x) {
        int grp   = gt >> 2;
        int slice = gt & 3;
        int r0 = grp * 4;
        const float4* xr0 = (const float4*)(x + (long)(r0 + 0) * FIN);
        const float4* xr1 = (const float4*)(x + (long)(r0 + 1) * FIN);
        const float4* xr2 = (const float4*)(x + (long)(r0 + 2) * FIN);
        const float4* xr3 = (const float4*)(x + (long)(r0 + 3) * FIN);
        unsigned long long acc[4][8];
        #pragma unroll
        for (int i = 0; i < 4; i++)
            #pragma unroll
            for (int j = 0; j < 8; j++) acc[i][j] = 0ull;
        const int cb = slice * 16;
        #pragma unroll 2
        for (int k4 = 0; k4 < FIN / 4; k4++) {
            float4 xv[4] = { xr0[k4], xr1[k4], xr2[k4], xr3[k4] };
            #pragma unroll
            for (int kk = 0; kk < 4; kk++) {
                const ulonglong2* wr = (const ulonglong2*)&Ws[(k4 * 4 + kk) * HID + cb];
                ulonglong2 p0 = wr[0], p1 = wr[1], p2 = wr[2], p3 = wr[3];
                unsigned long long w[8] = { p0.x, p0.y, p1.x, p1.y, p2.x, p2.y, p3.x, p3.y };
                #pragma unroll
                for (int i = 0; i < 4; i++) {
                    float xs = (kk == 0) ? xv[i].x : (kk == 1) ? xv[i].y
                             : (kk == 2) ? xv[i].z : xv[i].w;
                    unsigned long long xs2 = pack2(xs, xs);
                    #pragma unroll
                    for (int j = 0; j < 8; j++) ffma2(acc[i][j], xs2, w[j]);
                }
            }
        }
        #pragma unroll
        for (int i = 0; i < 4; i++) {
            ulonglong2* dst = (ulonglong2*)(g_HA + (long)(r0 + i) * HID + cb);
            #pragma unroll
            for (int j = 0; j < 4; j++)
                dst[j] = make_ulonglong2(acc[i][2 * j], acc[i][2 * j + 1]);
        }
    }
}

// spmm1: AG = relu(A_hat*H0 + b1)  (gather from g_HA, relu+bias epilogue)
__global__ void k_spmm1(const float* __restrict__ b1) {
    int i = (blockIdx.x * blockDim.x + threadIdx.x) >> 5;
    if (i >= NN) return;
    int lane = threadIdx.x & 31;
    int beg = g_ptr[i], end = g_ptr[i + 1];
    float  ns = g_nself[i];
    float2 h  = ((const float2*)(g_HA + (long)i * HID))[lane];
    float a0 = ns * h.x, a1 = ns * h.y;
    int e = beg;
    for (; e + 4 <= end; e += 4) {
        int2 r0 = g_csre[e + 0];
        int2 r1 = g_csre[e + 1];
        int2 r2 = g_csre[e + 2];
        int2 r3 = g_csre[e + 3];
        float2 v0 = ((const float2*)(g_HA + (long)r0.x * HID))[lane];
        float2 v1 = ((const float2*)(g_HA + (long)r1.x * HID))[lane];
        float2 v2 = ((const float2*)(g_HA + (long)r2.x * HID))[lane];
        float2 v3 = ((const float2*)(g_HA + (long)r3.x * HID))[lane];
        float n0 = __int_as_float(r0.y), n1 = __int_as_float(r1.y);
        float n2 = __int_as_float(r2.y), n3 = __int_as_float(r3.y);
        a0 += n0 * v0.x; a1 += n0 * v0.y;
        a0 += n1 * v1.x; a1 += n1 * v1.y;
        a0 += n2 * v2.x; a1 += n2 * v2.y;
        a0 += n3 * v3.x; a1 += n3 * v3.y;
    }
    for (; e < end; e++) {
        int2  rec = g_csre[e];
        float nm  = __int_as_float(rec.y);
        float2 v  = ((const float2*)(g_HA + (long)rec.x * HID))[lane];
        a0 += nm * v.x;
        a1 += nm * v.y;
    }
    float2 b = ((const float2*)b1)[lane];
    ((float2*)(g_AG + (long)i * HID))[lane] =
        make_float2(fmaxf(a0 + b.x, 0.f), fmaxf(a1 + b.y, 0.f));
}

// spmm2: HA = A_hat * H1   (gather from g_AG, plain epilogue)
__global__ void k_spmm2() {
    int i = (blockIdx.x * blockDim.x + threadIdx.x) >> 5;
    if (i >= NN) return;
    int lane = threadIdx.x & 31;
    int beg = g_ptr[i], end = g_ptr[i + 1];
    float  ns = g_nself[i];
    float2 h  = ((const float2*)(g_AG + (long)i * HID))[lane];
    float a0 = ns * h.x, a1 = ns * h.y;
    int e = beg;
    for (; e + 4 <= end; e += 4) {
        int2 r0 = g_csre[e + 0];
        int2 r1 = g_csre[e + 1];
        int2 r2 = g_csre[e + 2];
        int2 r3 = g_csre[e + 3];
        float2 v0 = ((const float2*)(g_AG + (long)r0.x * HID))[lane];
        float2 v1 = ((const float2*)(g_AG + (long)r1.x * HID))[lane];
        float2 v2 = ((const float2*)(g_AG + (long)r2.x * HID))[lane];
        float2 v3 = ((const float2*)(g_AG + (long)r3.x * HID))[lane];
        float n0 = __int_as_float(r0.y), n1 = __int_as_float(r1.y);
        float n2 = __int_as_float(r2.y), n3 = __int_as_float(r3.y);
        a0 += n0 * v0.x; a1 += n0 * v0.y;
        a0 += n1 * v1.x; a1 += n1 * v1.y;
        a0 += n2 * v2.x; a1 += n2 * v2.y;
        a0 += n3 * v3.x; a1 += n3 * v3.y;
    }
    for (; e < end; e++) {
        int2  rec = g_csre[e];
        float nm  = __int_as_float(rec.y);
        float2 v  = ((const float2*)(g_AG + (long)rec.x * HID))[lane];
        a0 += nm * v.x;
        a1 += nm * v.y;
    }
    ((float2*)(g_HA + (long)i * HID))[lane] = make_float2(a0, a1);
}

// out2: out = relu(P@W2 + b2) @ Wout + bout   (P in g_HA)
// 4 rows x 16-col slice per thread for the W2 GEMM; Wout tail reduced across
// the 4 slice threads (adjacent lanes) via shuffles.
__global__ void __launch_bounds__(256, 2)
k_out2(const float* __restrict__ W2, const float* __restrict__ b2,
       const float* __restrict__ Wout, const float* __restrict__ bout,
       float* __restrict__ out) {
    __shared__ float Ws[HID * HID];    // 16 KB
    __shared__ float Wo[HID * TOUT];   // 2.5 KB
    __shared__ float bs[HID];
    __shared__ float bo[TOUT];
    {
        const float4* w4 = (const float4*)W2;
        float4* s4 = (float4*)Ws;
        for (int i = threadIdx.x; i < HID * HID / 4; i += blockDim.x) s4[i] = w4[i];
        for (int i = threadIdx.x; i < HID * TOUT; i += blockDim.x) Wo[i] = Wout[i];
        if (threadIdx.x < HID)  bs[threadIdx.x] = b2[threadIdx.x];
        if (threadIdx.x < TOUT) bo[threadIdx.x] = bout[threadIdx.x];
    }
    __syncthreads();
    for (int gt = blockIdx.x * blockDim.x + threadIdx.x; gt < NG * 4;
         gt += gridDim.x * blockDim.x) {
        int grp   = gt >> 2;
        int slice = gt & 3;
        int r0 = grp * 4;
        const float4* p0p = (const float4*)(g_HA + (long)(r0 + 0) * HID);
        const float4* p1p = (const float4*)(g_HA + (long)(r0 + 1) * HID);
        const float4* p2p = (const float4*)(g_HA + (long)(r0 + 2) * HID);
        const float4* p3p = (const float4*)(g_HA + (long)(r0 + 3) * HID);
        unsigned long long acc[4][8];
        #pragma unroll
        for (int i = 0; i < 4; i++)
            #pragma unroll
            for (int j = 0; j < 8; j++) acc[i][j] = 0ull;
        const int cb = slice * 16;
        #pragma unroll 2
        for (int k4 = 0; k4 < HID / 4; k4++) {
            float4 pv[4] = { p0p[k4], p1p[k4], p2p[k4], p3p[k4] };
            #pragma unroll
            for (int kk = 0; kk < 4; kk++) {
                const ulonglong2* wr = (const ulonglong2*)&Ws[(k4 * 4 + kk) * HID + cb];
                ulonglong2 q0 = wr[0], q1 = wr[1], q2 = wr[2], q3 = wr[3];
                unsigned long long w[8] = { q0.x, q0.y, q1.x, q1.y, q2.x, q2.y, q3.x, q3.y };
                #pragma unroll
                for (int i = 0; i < 4; i++) {
                    float xs = (kk == 0) ? pv[i].x : (kk == 1) ? pv[i].y
                             : (kk == 2) ? pv[i].z : pv[i].w;
                    unsigned long long xs2 = pack2(xs, xs);
                    #pragma unroll
                    for (int j = 0; j < 8; j++) ffma2(acc[i][j], xs2, w[j]);
                }
            }
        }
        // Wout tail: per row, h2 slice (16 vals) -> partial out[10], then
        // shuffle-reduce over the 4 slice lanes.
        #pragma unroll
        for (int i = 0; i < 4; i++) {
            float pout[TOUT];
            #pragma unroll
            for (int o = 0; o < TOUT; o++) pout[o] = 0.f;
            #pragma unroll
            for (int j = 0; j < 8; j++) {
                float lo, hi;
                unpack2(acc[i][j], lo, hi);
                int c0 = cb + 2 * j;
                float h0 = fmaxf(lo + bs[c0],     0.f);
                float h1 = fmaxf(hi + bs[c0 + 1], 0.f);
                const float* w0 = &Wo[c0 * TOUT];
                const float* w1 = &Wo[(c0 + 1) * TOUT];
                #pragma unroll
                for (int o = 0; o < TOUT; o++) pout[o] += h0 * w0[o] + h1 * w1[o];
            }
            #pragma unroll
            for (int o = 0; o < TOUT; o++) {
                pout[o] += __shfl_xor_sync(0xffffffffu, pout[o], 1);
                pout[o] += __shfl_xor_sync(0xffffffffu, pout[o], 2);
            }
            if (slice == 0) {
                float* od = out + (long)(r0 + i) * TOUT;
                #pragma unroll
                for (int o = 0; o < TOUT; o++) od[o] = pout[o] + bo[o];
            }
        }
    }
}

// ---------------- launch ----------------
extern "C" void kernel_launch(void* const* d_in, const int* in_sizes, int n_in,
                              void* d_out, int out_size) {
    const float* x    = (const float*)d_in[0];
    const int*   ei   = (const int*)d_in[1];
    const float* et   = (const float*)d_in[2];
    const float* W1   = (const float*)d_in[3];
    const float* b1   = (const float*)d_in[4];
    const float* W2   = (const float*)d_in[5];
    const float* b2   = (const float*)d_in[6];
    const float* Wout = (const float*)d_in[7];
    const float* bout = (const float*)d_in[8];
    float*       out  = (float*)d_out;

    const int TB = 256;
    const int GEMMB = 2 * NSM;          // one full resident wave

    cudaStream_t s2;
    cudaEvent_t  eFork, eJoin;
    cudaStreamCreateWithFlags(&s2, cudaStreamNonBlocking);
    cudaEventCreateWithFlags(&eFork, cudaEventDisableTiming);
    cudaEventCreateWithFlags(&eJoin, cudaEventDisableTiming);

    // fork: gemm1 runs concurrently with the edge-preprocessing chain
    cudaEventRecord(eFork, 0);
    cudaStreamWaitEvent(s2, eFork, 0);
    k_gemm1<<<GEMMB, TB, 0, s2>>>(x, W1);
    cudaEventRecord(eJoin, s2);

    // main stream: edge preprocessing -> CSR (R14 structure)
    k_detect_zero<<<NB, TB>>>(ei);
    k_decay_deg<<<(NE + TB - 1) / TB, TB>>>(ei, et);
    k_ew_deg2<<<(NE + TB - 1) / TB, TB>>>();
    k_scanA<<<NB, TB>>>();
    k_scanC<<<NB, TB>>>();
    k_fill <<<(NE + TB - 1) / TB, TB>>>();

    // join: spmm needs both HA (gemm1) and CSR (fill)
    cudaStreamWaitEvent(0, eJoin, 0);

    k_spmm1<<<(NN * 32 + TB - 1) / TB, TB>>>(b1);   // AG = relu(A*H0 + b1)
    k_spmm2<<<(NN * 32 + TB - 1) / TB, TB>>>();     // HA = A*H1
    k_out2 <<<GEMMB, TB>>>(W2, b2, Wout, bout, out);
}